// round 1
// baseline (speedup 1.0000x reference)
#include <cuda_runtime.h>
#include <stdint.h>

// ---------------- problem constants ----------------
#define BATCH 128
#define TSTEPS 300
#define CLIP 50
#define DIN 2312
#define DINP 2320          // K padded to multiple of 8
#define HID 800
#define HIDP 896           // N padded to multiple of 128
#define NC 10
#define MROWS (BATCH*CLIP) // 6400

// ---------------- scratch (static device globals; no allocs) ----------------
__device__ float g_Xc[(size_t)MROWS * DINP];   // transposed+padded clips  [6400][2320]
__device__ float g_W1p[(size_t)HIDP * DINP];   // padded W1                [896][2320]
__device__ float g_V1[(size_t)MROWS * HIDP];   // V1 = x @ W1.T            [6400][896]

// ---------------- kernel 1: write output X (paste) ----------------
// out layout assumed: [rate(128*10)][X(128*2312*300)]
__global__ void paste_kernel(const float* __restrict__ inp,
                             const int* __restrict__ idx,
                             float* __restrict__ outX) {
    long tid = (long)blockIdx.x * blockDim.x + threadIdx.x;  // one float4 along t
    const long total = (long)BATCH * DIN * (TSTEPS / 4);
    if (tid >= total) return;
    int  c4  = (int)(tid % (TSTEPS / 4));
    long row = tid / (TSTEPS / 4);
    int  i   = (int)(row / DIN);
    int  d   = (int)(row % DIN);
    int  t0  = c4 * 4;
    int  id  = idx[i];
    float4 v;
    float* vv = (float*)&v;
    const float* src = inp + (long)i * DIN * CLIP + (long)d * CLIP;
#pragma unroll
    for (int u = 0; u < 4; u++) {
        int s = t0 + u - id;
        vv[u] = (s >= 0 && s < CLIP) ? src[s] : 0.f;
    }
    *(float4*)&outX[row * TSTEPS + t0] = v;
}

// ---------------- kernel 2: transpose clips into Xc [6400][2320] ----------------
__global__ void transpose_kernel(const float* __restrict__ inp) {
    __shared__ float tile[32][51];
    int i  = blockIdx.x;
    int d0 = blockIdx.y * 32;
    int tid = threadIdx.x;  // 256
    for (int p = tid; p < 32 * CLIP; p += 256) {
        int dd = p / CLIP, s = p % CLIP;
        int d = d0 + dd;
        tile[dd][s] = (d < DIN) ? inp[(long)i * DIN * CLIP + (long)d * CLIP + s] : 0.f;
    }
    __syncthreads();
    for (int p = tid; p < CLIP * 32; p += 256) {
        int s = p / 32, dd = p % 32;
        int d = d0 + dd;
        if (d < DINP)
            g_Xc[((long)i * CLIP + s) * DINP + d] = tile[dd][s];
    }
}

// ---------------- kernel 3: pad W1 -> W1p [896][2320] ----------------
__global__ void w1pad_kernel(const float* __restrict__ W1) {
    long t = (long)blockIdx.x * blockDim.x + threadIdx.x;
    if (t >= (long)HIDP * DINP) return;
    int n = (int)(t / DINP), k = (int)(t % DINP);
    g_W1p[t] = (n < HID && k < DIN) ? W1[(long)n * DIN + k] : 0.f;
}

// ---------------- kernel 4: fp32 GEMM via packed f32x2 FFMA ----------------
typedef unsigned long long ull;
__device__ __forceinline__ void ffma2(ull& d, ull a, ull b) {
    asm("fma.rn.f32x2 %0, %1, %2, %0;" : "+l"(d) : "l"(a), "l"(b));
}
__device__ __forceinline__ ull pack2(float x) {
    ull r; asm("mov.b64 %0, {%1, %1};" : "=l"(r) : "f"(x)); return r;
}

#define BM 128
#define BN 128
#define BK 8

__global__ __launch_bounds__(256, 2) void gemm_kernel() {
    __shared__ __align__(16) float As[BK][BM];
    __shared__ __align__(16) float Bs[BK][BN];
    int m0 = blockIdx.x * BM;
    int n0 = blockIdx.y * BN;
    int tid = threadIdx.x;
    int tx = tid & 15;        // 16 threads over N (8 each)
    int ty = tid >> 4;        // 16 threads over M (8 each)
    int lrow = tid >> 1;      // 0..127 load row
    int lk4  = (tid & 1) * 4; // 0 or 4

    ull acc[8][4];
#pragma unroll
    for (int r = 0; r < 8; r++)
#pragma unroll
        for (int q = 0; q < 4; q++) acc[r][q] = 0ull;

    const float* Ag = &g_Xc[(long)(m0 + lrow) * DINP + lk4];
    const float* Bg = &g_W1p[(long)(n0 + lrow) * DINP + lk4];

    for (int k0 = 0; k0 < DINP; k0 += BK) {
        float4 av = *(const float4*)(Ag + k0);
        float4 bv = *(const float4*)(Bg + k0);
        __syncthreads();
        As[lk4 + 0][lrow] = av.x; As[lk4 + 1][lrow] = av.y;
        As[lk4 + 2][lrow] = av.z; As[lk4 + 3][lrow] = av.w;
        Bs[lk4 + 0][lrow] = bv.x; Bs[lk4 + 1][lrow] = bv.y;
        Bs[lk4 + 2][lrow] = bv.z; Bs[lk4 + 3][lrow] = bv.w;
        __syncthreads();
#pragma unroll
        for (int kk = 0; kk < BK; kk++) {
            float4 a0 = *(const float4*)&As[kk][ty * 8];
            float4 a1 = *(const float4*)&As[kk][ty * 8 + 4];
            ull bq[4];
#pragma unroll
            for (int q = 0; q < 4; q++)
                bq[q] = *(const ull*)&Bs[kk][tx * 8 + q * 2];
            ull ar[8];
            ar[0] = pack2(a0.x); ar[1] = pack2(a0.y);
            ar[2] = pack2(a0.z); ar[3] = pack2(a0.w);
            ar[4] = pack2(a1.x); ar[5] = pack2(a1.y);
            ar[6] = pack2(a1.z); ar[7] = pack2(a1.w);
#pragma unroll
            for (int r = 0; r < 8; r++)
#pragma unroll
                for (int q = 0; q < 4; q++)
                    ffma2(acc[r][q], ar[r], bq[q]);
        }
    }

#pragma unroll
    for (int r = 0; r < 8; r++) {
        long m = m0 + ty * 8 + r;
        float2 f0 = *(float2*)&acc[r][0];
        float2 f1 = *(float2*)&acc[r][1];
        float2 f2 = *(float2*)&acc[r][2];
        float2 f3 = *(float2*)&acc[r][3];
        float* dst = &g_V1[m * HIDP + n0 + tx * 8];
        *(float4*)(dst + 0) = make_float4(f0.x, f0.y, f1.x, f1.y);
        *(float4*)(dst + 4) = make_float4(f2.x, f2.y, f3.x, f3.y);
    }
}

// ---------------- kernel 5: the sequential scan (1 CTA per batch row) ----------------
__global__ __launch_bounds__(256, 1) void scan_kernel(
    const int*   __restrict__ idx,
    const float* __restrict__ b1,
    const float* __restrict__ W2,   // [10][800]
    const float* __restrict__ b2,   // [10]
    const float* __restrict__ Wc,   // [804]
    const float* __restrict__ bc,   // [1]
    float*       __restrict__ out)  // rate at out[0..1280)
{
    __shared__ float W2t[HID][NC];  // transposed W2 for per-neuron access
    __shared__ float Wcs[HID];
    __shared__ float b1s[HID];
    __shared__ float wpart[8][11];
    __shared__ float cs_sh;
    __shared__ float bgt_sh;

    int i   = blockIdx.x;
    int tid = threadIdx.x;

    for (int p = tid; p < HID * NC; p += 256) {
        int k = p / HID, j = p % HID;
        W2t[j][k] = W2[p];     // W2[k*800 + j]
    }
    for (int p = tid; p < HID; p += 256) { Wcs[p] = Wc[p]; b1s[p] = b1[p]; }
    if (tid == 0) cs_sh = 0.f;

    float h1m[4] = {0.f, 0.f, 0.f, 0.f};
    float h1s[4] = {0.f, 0.f, 0.f, 0.f};
    int  jj[4]; bool jv[4];
#pragma unroll
    for (int r = 0; r < 4; r++) { jj[r] = tid + 256 * r; jv[r] = (jj[r] < HID); }

    // tid<10 owns h2 channel tid; tid==10 owns controller
    float h2m = 0.f, h2s = 0.f, sum2 = 0.f, my_b2 = 0.f;
    float cm = 0.f, bgt = 1.f;
    float wc0 = 0.f, wc1 = 0.f, wc2 = 0.f, wc3 = 0.f, bc0 = 0.f;
    if (tid < 10) my_b2 = b2[tid];
    if (tid == 10) {
        wc0 = Wc[800]; wc1 = Wc[801]; wc2 = Wc[802]; wc3 = Wc[803];
        bc0 = bc[0];
    }
    int myidx = idx[i];
    __syncthreads();

    for (int t = 0; t < TSTEPS; t++) {
        float g = (t == 0) ? 1.f : cs_sh;
        int s = t - myidx;
        bool act = (s >= 0) && (s < CLIP) && (g != 0.f);
        int srow = act ? s : 0;
        const float* v1 = &g_V1[((long)i * CLIP + srow) * HIDP];

        float part[11];
#pragma unroll
        for (int k = 0; k < 11; k++) part[k] = 0.f;

#pragma unroll
        for (int r = 0; r < 4; r++) {
            if (jv[r]) {
                float v = act ? g * v1[jj[r]] : 0.f;
                float m = h1m[r] * 0.1f * (1.f - h1s[r]) + v + b1s[jj[r]];
                h1m[r] = m;
                float sp = (m > 0.5f) ? 1.f : 0.f;
                h1s[r] = sp;
                if (sp != 0.f) {
#pragma unroll
                    for (int k = 0; k < 10; k++) part[k] += W2t[jj[r]][k];
                    part[10] += Wcs[jj[r]];
                }
            }
        }
        // deterministic warp reduce (fixed order)
#pragma unroll
        for (int k = 0; k < 11; k++) {
#pragma unroll
            for (int off = 16; off; off >>= 1)
                part[k] += __shfl_down_sync(0xffffffffu, part[k], off);
        }
        if ((tid & 31) == 0) {
#pragma unroll
            for (int k = 0; k < 11; k++) wpart[tid >> 5][k] = part[k];
        }
        __syncthreads();   // wpart visible; all cs_sh reads for this step done

        if (tid < 10) {
            float red = 0.f;
#pragma unroll
            for (int w = 0; w < 8; w++) red += wpart[w][tid];
            float m = h2m * 0.1f * (1.f - h2s) + red + my_b2;
            h2m = m;
            h2s = (m > 0.5f) ? 1.f : 0.f;
            sum2 += h2s;
        } else if (tid == 10) {
            float red = 0.f;
#pragma unroll
            for (int w = 0; w < 8; w++) red += wpart[w][10];
            float csprev = cs_sh;
            if (csprev == 1.f) bgt += 1.f;
            float fq = wc0
                     + (((t % 2)   == 0) ? wc1 : 0.f)
                     + (((t % 10)  == 0) ? wc2 : 0.f)
                     + (((t % 100) == 0) ? wc3 : 0.f);
            cm = cm * 0.1f * (1.f - csprev) + red + fq + bc0;
            cs_sh = (cm > 0.5f) ? 1.f : 0.f;
        }
        __syncthreads();   // cs_sh update visible for next step; wpart reads done
    }

    if (tid == 10) bgt_sh = bgt;
    __syncthreads();
    if (tid < 10) out[i * NC + tid] = sum2 / bgt_sh;
}

// ---------------- launcher ----------------
extern "C" void kernel_launch(void* const* d_in, const int* in_sizes, int n_in,
                              void* d_out, int out_size) {
    const float* inp = (const float*)d_in[0];   // [128,2,34,34,50]
    /* d_in[1] = X (zeros) unused */
    const int*   idx = (const int*)d_in[2];     // [128]
    const float* W1  = (const float*)d_in[3];   // [800,2312]
    const float* b1  = (const float*)d_in[4];   // [800]
    const float* W2  = (const float*)d_in[5];   // [10,800]
    const float* b2  = (const float*)d_in[6];   // [10]
    const float* Wc  = (const float*)d_in[7];   // [1,804]
    const float* bc  = (const float*)d_in[8];   // [1]
    float* out = (float*)d_out;

    // 1) write X output (paste) — independent of everything else
    {
        long total = (long)BATCH * DIN * (TSTEPS / 4);
        int blocks = (int)((total + 255) / 256);
        paste_kernel<<<blocks, 256>>>(inp, idx, out + BATCH * NC);
    }
    // 2) transpose clips into Xc
    {
        dim3 grid(BATCH, (DINP + 31) / 32);
        transpose_kernel<<<grid, 256>>>(inp);
    }
    // 3) pad W1
    {
        long total = (long)HIDP * DINP;
        int blocks = (int)((total + 255) / 256);
        w1pad_kernel<<<blocks, 256>>>(W1);
    }
    // 4) V1 = Xc @ W1p^T
    {
        dim3 grid(MROWS / BM, HIDP / BN);
        gemm_kernel<<<grid, 256>>>();
    }
    // 5) sequential scan, one CTA per batch row; writes rate to out[0..1280)
    scan_kernel<<<BATCH, 256>>>(idx, b1, W2, b2, Wc, bc, out);
}